// round 10
// baseline (speedup 1.0000x reference)
#include <cuda_runtime.h>
#include <cuda_bf16.h>
#include <cstdint>

// ---------------- problem constants ----------------
#define K_TOTAL 33154
#define SEG1    16641
#define SEG2    16770
#define AT_LEN  129
#define ST1_LEN 16384
#define NBATCH  1024
#define NHID    512
#define NOUT    129

// ---------------- padded / tiling constants ----------------
#define SPLITK  9
#define CK      32
#define NCHUNK  116
#define KSPLIT  (NCHUNK * CK)        // 3712
#define KPAD    (SPLITK * KSPLIT)    // 33408
#define TM      64
#define TN      512
#define MT      (NBATCH / TM)        // 16 -> grid 16*1*9 = 144 CTAs (one wave)

// ---------------- device scratch ----------------
__device__ float g_hpart[SPLITK][NBATCH][NHID];                 // 18 MB
__device__ __align__(128) __nv_bfloat16 g_xh[NBATCH][KPAD];
__device__ __align__(128) __nv_bfloat16 g_xl[NBATCH][KPAD];
__device__ __align__(128) __nv_bfloat16 g_wh[NHID][KPAD];
__device__ __align__(128) __nv_bfloat16 g_wl[NHID][KPAD];

// ---------------- helpers ----------------
__device__ __forceinline__ uint32_t smem_u32(const void* p) {
    uint32_t a;
    asm("{ .reg .u64 t; cvta.to.shared.u64 t, %1; cvt.u32.u64 %0, t; }"
        : "=r"(a) : "l"(p));
    return a;
}
// SW64 swizzle for 64-byte rows (8-row atom covers all 8 16B bank groups)
#define SWZ64(o) (((uint32_t)(o)) ^ ((((uint32_t)(o)) >> 3) & 0x30u))

__device__ __forceinline__ void cp_async16(uint32_t dst, const void* src) {
    asm volatile("cp.async.cg.shared.global [%0], [%1], 16;" :: "r"(dst), "l"(src) : "memory");
}
#define CP_COMMIT() asm volatile("cp.async.commit_group;" ::: "memory")
#define CP_WAIT1()  asm volatile("cp.async.wait_group 1;" ::: "memory")
#define CP_WAIT0()  asm volatile("cp.async.wait_group 0;" ::: "memory")

#define LDM_X4(r0, r1, r2, r3, a) \
    asm volatile("ldmatrix.sync.aligned.m8n8.x4.shared.b16 {%0,%1,%2,%3}, [%4];" \
                 : "=r"(r0), "=r"(r1), "=r"(r2), "=r"(r3) : "r"(a))

__device__ __forceinline__ void mma_bf16(float* c, const uint32_t* a, const uint32_t* b) {
    asm volatile(
        "mma.sync.aligned.m16n8k16.row.col.f32.bf16.bf16.f32 "
        "{%0,%1,%2,%3}, {%4,%5,%6,%7}, {%8,%9}, {%0,%1,%2,%3};"
        : "+f"(c[0]), "+f"(c[1]), "+f"(c[2]), "+f"(c[3])
        : "r"(a[0]), "r"(a[1]), "r"(a[2]), "r"(a[3]), "r"(b[0]), "r"(b[1]));
}

// ---------------- x concat access ----------------
__device__ __forceinline__ float load_x(const float* __restrict__ st,
                                        const float* __restrict__ at,
                                        const float* __restrict__ st1,
                                        int b, int k) {
    if (k < SEG1)  return st [b * SEG1    + k];
    if (k < SEG2)  return at [b * AT_LEN  + (k - SEG1)];
    return st1[b * ST1_LEN + (k - SEG2)];
}

// ======================================================================
// convert_x: x -> (xh, xl) bf16 split, zero-padded to KPAD.
// 8 elements per thread -> one STG.128 per array.
// ======================================================================
__global__ void __launch_bounds__(256)
convert_x_kernel(const float* __restrict__ st, const float* __restrict__ at,
                 const float* __restrict__ st1)
{
    const int m = blockIdx.y;
    const int k = (blockIdx.x * 256 + threadIdx.x) * 8;
    if (k >= KPAD) return;
    float v[8];
    #pragma unroll
    for (int i = 0; i < 8; i++)
        v[i] = (k + i < K_TOTAL) ? load_x(st, at, st1, m, k + i) : 0.0f;

    uint32_t hp[4], lp[4];
    #pragma unroll
    for (int i = 0; i < 4; i++) {
        __nv_bfloat16 h0 = __float2bfloat16(v[2*i]);
        __nv_bfloat16 h1 = __float2bfloat16(v[2*i+1]);
        __nv_bfloat16 l0 = __float2bfloat16(v[2*i]   - __bfloat162float(h0));
        __nv_bfloat16 l1 = __float2bfloat16(v[2*i+1] - __bfloat162float(h1));
        __nv_bfloat162 hh(h0, h1), ll(l0, l1);
        hp[i] = *reinterpret_cast<uint32_t*>(&hh);
        lp[i] = *reinterpret_cast<uint32_t*>(&ll);
    }
    *reinterpret_cast<uint4*>(&g_xh[m][k]) = make_uint4(hp[0], hp[1], hp[2], hp[3]);
    *reinterpret_cast<uint4*>(&g_xl[m][k]) = make_uint4(lp[0], lp[1], lp[2], lp[3]);
}

// ======================================================================
// convert_w: W1 [K][512] fp32 -> transposed (wh, wl) [512][KPAD] bf16.
// ======================================================================
__global__ void __launch_bounds__(256)
convert_w_kernel(const float* __restrict__ W1)
{
    __shared__ float tile[32][33];
    const int k0 = blockIdx.x * 32;
    const int n0 = blockIdx.y * 32;
    const int tx = threadIdx.x, ty = threadIdx.y;

    #pragma unroll
    for (int i = 0; i < 4; i++) {
        int k = k0 + ty + i * 8;
        tile[ty + i * 8][tx] = (k < K_TOTAL) ? W1[(size_t)k * NHID + n0 + tx] : 0.0f;
    }
    __syncthreads();
    #pragma unroll
    for (int i = 0; i < 4; i++) {
        int n = n0 + ty + i * 8;
        float v = tile[tx][ty + i * 8];
        __nv_bfloat16 h = __float2bfloat16(v);
        __nv_bfloat16 l = __float2bfloat16(v - __bfloat162float(h));
        g_wh[n][k0 + tx] = h;
        g_wl[n][k0 + tx] = l;
    }
}

// ======================================================================
// GEMM1: CTA tile 64(M) x 512(N), NT=1 so x is read exactly once.
// Split-K over z (9 splits), chunks of K=32 (64-byte rows, SW64 swizzle).
// Per-chunk smem: xh,xl 4KB each + wh,wl 32KB each = 72KB; double = 144KB.
// 8 warps in a row: warp tile 64(M) x 64(N) (identical inner structure to
// the verified R7 kernel). 3 bf16 passes accumulated in fp32.
// ======================================================================
__global__ void __launch_bounds__(256, 1)
gemm_mma_kernel()
{
    extern __shared__ char dyn_smem[];
    const uint32_t base = (smem_u32(dyn_smem) + 1023u) & ~1023u;

    const int tid  = threadIdx.x;
    const int wid  = tid >> 5;
    const int lane = tid & 31;

    const int m0 = blockIdx.x * TM;
    const int split = blockIdx.z;
    const int kbase = split * KSPLIT;

    const int nwarp = wid * 64;          // 8 warps cover N=512

    const int a_row = lane & 15;
    const int a_col = (lane >> 4) * 16;
    const int b_row = (lane & 7) + ((lane >> 4) << 3);
    const int b_col = ((lane >> 3) & 1) * 16;

    float c[4][8][4];
    #pragma unroll
    for (int i = 0; i < 4; i++)
        #pragma unroll
        for (int j = 0; j < 8; j++)
            #pragma unroll
            for (int e = 0; e < 4; e++) c[i][j][e] = 0.0f;

    // buffer layout: Ah 0, Al 4K, Bh 8K, Bl 40K; BUFSZ 72K
    const uint32_t OFF_AL = 4096u, OFF_BH = 8192u, OFF_BL = 40960u;
    const uint32_t BUFSZ = 73728u;

    auto issue_loads = [&](int ch) {
        const int k0 = kbase + ch * CK;
        const uint32_t buf = base + ((ch & 1) ? BUFSZ : 0u);
        // A: 64 rows x 4 quads = 256 quads per array (1 per thread each)
        {
            int row = tid >> 2, qc = tid & 3;
            uint32_t off = SWZ64(row * 64 + qc * 16);
            cp_async16(buf +          off, &g_xh[m0 + row][k0 + qc * 8]);
            cp_async16(buf + OFF_AL + off, &g_xl[m0 + row][k0 + qc * 8]);
        }
        // B: 512 rows x 4 quads = 2048 quads per array (8 per thread each)
        #pragma unroll
        for (int t = 0; t < 8; t++) {
            int q = tid + t * 256;
            int row = q >> 2, qc = q & 3;
            uint32_t off = SWZ64(row * 64 + qc * 16);
            cp_async16(buf + OFF_BH + off, &g_wh[row][k0 + qc * 8]);
            cp_async16(buf + OFF_BL + off, &g_wl[row][k0 + qc * 8]);
        }
        CP_COMMIT();
    };

    issue_loads(0);

    for (int i = 0; i < NCHUNK; i++) {
        if (i + 1 < NCHUNK) { issue_loads(i + 1); CP_WAIT1(); }
        else                { CP_WAIT0(); }
        __syncthreads();

        const uint32_t buf = base + ((i & 1) ? BUFSZ : 0u);
        const uint32_t Ah = buf, Al = buf + OFF_AL;
        const uint32_t Bh = buf + OFF_BH, Bl = buf + OFF_BL;

        #pragma unroll
        for (int kk = 0; kk < 2; kk++) {
            uint32_t ah[4][4], al[4][4];
            #pragma unroll
            for (int t = 0; t < 4; t++) {
                uint32_t offA = SWZ64((t * 16 + a_row) * 64 + kk * 32 + a_col);
                LDM_X4(ah[t][0], ah[t][1], ah[t][2], ah[t][3], Ah + offA);
                LDM_X4(al[t][0], al[t][1], al[t][2], al[t][3], Al + offA);
            }
            #pragma unroll
            for (int half = 0; half < 2; half++) {
                uint32_t bh[4][2], bl[4][2];
                #pragma unroll
                for (int t = 0; t < 2; t++) {
                    uint32_t offB = SWZ64((nwarp + half * 32 + t * 16 + b_row) * 64
                                          + kk * 32 + b_col);
                    LDM_X4(bh[2*t][0], bh[2*t][1], bh[2*t+1][0], bh[2*t+1][1], Bh + offB);
                    LDM_X4(bl[2*t][0], bl[2*t][1], bl[2*t+1][0], bl[2*t+1][1], Bl + offB);
                }
                #pragma unroll
                for (int mi = 0; mi < 4; mi++)
                    #pragma unroll
                    for (int nj = 0; nj < 4; nj++) {
                        float* acc = c[mi][half * 4 + nj];
                        mma_bf16(acc, ah[mi], bh[nj]);   // xh * wh
                        mma_bf16(acc, ah[mi], bl[nj]);   // xh * wl
                        mma_bf16(acc, al[mi], bh[nj]);   // xl * wh
                    }
            }
        }
        __syncthreads();
    }

    // epilogue: m16n8 frag -> rows (lane/4, +8), cols 2*(lane%4)
    const int er = lane >> 2;
    const int ec = (lane & 3) * 2;
    #pragma unroll
    for (int mi = 0; mi < 4; mi++) {
        const int row = m0 + mi * 16 + er;
        #pragma unroll
        for (int nj = 0; nj < 8; nj++) {
            const int col = nwarp + nj * 8 + ec;
            *reinterpret_cast<float2*>(&g_hpart[split][row][col]) =
                make_float2(c[mi][nj][0], c[mi][nj][1]);
            *reinterpret_cast<float2*>(&g_hpart[split][row + 8][col]) =
                make_float2(c[mi][nj][2], c[mi][nj][3]);
        }
    }
}

// ======================================================================
// Stage 2 (reverted to the verified 26us shape): one CTA per batch row.
// Reduce split-K partials, +b1, ReLU, then h @ W2 + b2.
// ======================================================================
__global__ void __launch_bounds__(256)
mlp2_kernel(const float* __restrict__ b1,
            const float* __restrict__ W2,
            const float* __restrict__ b2,
            float* __restrict__ out)
{
    __shared__ float hs[NHID];
    const int b   = blockIdx.x;
    const int tid = threadIdx.x;

    #pragma unroll
    for (int n = tid; n < NHID; n += 256) {
        float s = 0.0f;
        #pragma unroll
        for (int sp = 0; sp < SPLITK; sp++) s += g_hpart[sp][b][n];
        s += b1[n];
        hs[n] = fmaxf(s, 0.0f);
    }
    __syncthreads();

    if (tid < NOUT) {
        float a0 = 0.f, a1 = 0.f, a2 = 0.f, a3 = 0.f;
        #pragma unroll 8
        for (int n = 0; n < NHID; n += 4) {
            a0 = fmaf(hs[n + 0], W2[(n + 0) * NOUT + tid], a0);
            a1 = fmaf(hs[n + 1], W2[(n + 1) * NOUT + tid], a1);
            a2 = fmaf(hs[n + 2], W2[(n + 2) * NOUT + tid], a2);
            a3 = fmaf(hs[n + 3], W2[(n + 3) * NOUT + tid], a3);
        }
        out[b * NOUT + tid] = (a0 + a1) + (a2 + a3) + b2[tid];
    }
}

// ======================================================================
// kernel_launch — graph-capturable, allocation-free.
// Input order (metadata): st, at, st1, W1, b1, W2, b2. Output: float32.
// ======================================================================
extern "C" void kernel_launch(void* const* d_in, const int* in_sizes, int n_in,
                              void* d_out, int out_size)
{
    const float* st  = (const float*)d_in[0];
    const float* at  = (const float*)d_in[1];
    const float* st1 = (const float*)d_in[2];
    const float* W1  = (const float*)d_in[3];
    const float* b1  = (const float*)d_in[4];
    const float* W2  = (const float*)d_in[5];
    const float* b2  = (const float*)d_in[6];
    float* out = (float*)d_out;

    dim3 gx((KPAD + 2047) / 2048, NBATCH);
    convert_x_kernel<<<gx, 256>>>(st, at, st1);

    dim3 gw(KPAD / 32, NHID / 32);
    convert_w_kernel<<<gw, dim3(32, 8)>>>(W1);

    const int dyn_smem = 2 * 73728 + 1024;   // 144 KB + align slack
    cudaFuncSetAttribute(gemm_mma_kernel,
                         cudaFuncAttributeMaxDynamicSharedMemorySize, dyn_smem);
    dim3 gg(MT, 1, SPLITK);                  // 16 x 1 x 9 = 144 CTAs, one wave
    gemm_mma_kernel<<<gg, 256, dyn_smem>>>();

    mlp2_kernel<<<NBATCH, 256>>>(b1, W2, b2, out);
}

// round 11
// speedup vs baseline: 1.1590x; 1.1590x over previous
#include <cuda_runtime.h>
#include <cuda_bf16.h>
#include <cstdint>

// ---------------- problem constants ----------------
#define K_TOTAL 33154
#define SEG1    16641
#define SEG2    16770
#define AT_LEN  129
#define ST1_LEN 16384
#define NBATCH  1024
#define NHID    512
#define NOUT    129

// ---------------- padded / tiling constants ----------------
#define SPLITK  9
#define CK      64
#define NCHUNK  58
#define KSPLIT  (NCHUNK * CK)        // 3712
#define KPAD    (SPLITK * KSPLIT)    // 33408
#define TM      128
#define TN      256
#define MT      (NBATCH / TM)        // 8
#define NT      (NHID  / TN)         // 2  -> grid 8*2*9 = 144 CTAs (one wave)

// ---------------- device scratch ----------------
__device__ float g_hpart[SPLITK][NBATCH][NHID];                 // 18 MB
__device__ __align__(128) __nv_bfloat16 g_xh[NBATCH][KPAD];
__device__ __align__(128) __nv_bfloat16 g_xl[NBATCH][KPAD];
__device__ __align__(128) __nv_bfloat16 g_wh[NHID][KPAD];
__device__ __align__(128) __nv_bfloat16 g_wl[NHID][KPAD];

// ---------------- helpers ----------------
__device__ __forceinline__ uint32_t smem_u32(const void* p) {
    uint32_t a;
    asm("{ .reg .u64 t; cvta.to.shared.u64 t, %1; cvt.u32.u64 %0, t; }"
        : "=r"(a) : "l"(p));
    return a;
}
#define SWZ128(o) (((uint32_t)(o)) ^ ((((uint32_t)(o)) >> 3) & 0x70u))

__device__ __forceinline__ void cp_async16(uint32_t dst, const void* src) {
    asm volatile("cp.async.cg.shared.global [%0], [%1], 16;" :: "r"(dst), "l"(src) : "memory");
}
#define CP_COMMIT() asm volatile("cp.async.commit_group;" ::: "memory")
#define CP_WAIT1()  asm volatile("cp.async.wait_group 1;" ::: "memory")
#define CP_WAIT0()  asm volatile("cp.async.wait_group 0;" ::: "memory")

#define LDM_X4(r0, r1, r2, r3, a) \
    asm volatile("ldmatrix.sync.aligned.m8n8.x4.shared.b16 {%0,%1,%2,%3}, [%4];" \
                 : "=r"(r0), "=r"(r1), "=r"(r2), "=r"(r3) : "r"(a))

__device__ __forceinline__ void mma_bf16(float* c, const uint32_t* a, const uint32_t* b) {
    asm volatile(
        "mma.sync.aligned.m16n8k16.row.col.f32.bf16.bf16.f32 "
        "{%0,%1,%2,%3}, {%4,%5,%6,%7}, {%8,%9}, {%0,%1,%2,%3};"
        : "+f"(c[0]), "+f"(c[1]), "+f"(c[2]), "+f"(c[3])
        : "r"(a[0]), "r"(a[1]), "r"(a[2]), "r"(a[3]), "r"(b[0]), "r"(b[1]));
}

// ---------------- x concat access ----------------
__device__ __forceinline__ float load_x(const float* __restrict__ st,
                                        const float* __restrict__ at,
                                        const float* __restrict__ st1,
                                        int b, int k) {
    if (k < SEG1)  return st [b * SEG1    + k];
    if (k < SEG2)  return at [b * AT_LEN  + (k - SEG1)];
    return st1[b * ST1_LEN + (k - SEG2)];
}

// ======================================================================
// convert_x: x -> (xh, xl) bf16 split, zero-padded to KPAD.
// 8 elements per thread -> one STG.128 per array.
// ======================================================================
__global__ void __launch_bounds__(256)
convert_x_kernel(const float* __restrict__ st, const float* __restrict__ at,
                 const float* __restrict__ st1)
{
    const int m = blockIdx.y;
    const int k = (blockIdx.x * 256 + threadIdx.x) * 8;
    if (k >= KPAD) return;
    float v[8];
    #pragma unroll
    for (int i = 0; i < 8; i++)
        v[i] = (k + i < K_TOTAL) ? load_x(st, at, st1, m, k + i) : 0.0f;

    uint32_t hp[4], lp[4];
    #pragma unroll
    for (int i = 0; i < 4; i++) {
        __nv_bfloat16 h0 = __float2bfloat16(v[2*i]);
        __nv_bfloat16 h1 = __float2bfloat16(v[2*i+1]);
        __nv_bfloat16 l0 = __float2bfloat16(v[2*i]   - __bfloat162float(h0));
        __nv_bfloat16 l1 = __float2bfloat16(v[2*i+1] - __bfloat162float(h1));
        __nv_bfloat162 hh(h0, h1), ll(l0, l1);
        hp[i] = *reinterpret_cast<uint32_t*>(&hh);
        lp[i] = *reinterpret_cast<uint32_t*>(&ll);
    }
    *reinterpret_cast<uint4*>(&g_xh[m][k]) = make_uint4(hp[0], hp[1], hp[2], hp[3]);
    *reinterpret_cast<uint4*>(&g_xl[m][k]) = make_uint4(lp[0], lp[1], lp[2], lp[3]);
}

// ======================================================================
// convert_w: W1 [K][512] fp32 -> transposed (wh, wl) [512][KPAD] bf16.
// ======================================================================
__global__ void __launch_bounds__(256)
convert_w_kernel(const float* __restrict__ W1)
{
    __shared__ float tile[32][33];
    const int k0 = blockIdx.x * 32;
    const int n0 = blockIdx.y * 32;
    const int tx = threadIdx.x, ty = threadIdx.y;

    #pragma unroll
    for (int i = 0; i < 4; i++) {
        int k = k0 + ty + i * 8;
        tile[ty + i * 8][tx] = (k < K_TOTAL) ? W1[(size_t)k * NHID + n0 + tx] : 0.0f;
    }
    __syncthreads();
    #pragma unroll
    for (int i = 0; i < 4; i++) {
        int n = n0 + ty + i * 8;
        float v = tile[tx][ty + i * 8];
        __nv_bfloat16 h = __float2bfloat16(v);
        __nv_bfloat16 l = __float2bfloat16(v - __bfloat162float(h));
        g_wh[n][k0 + tx] = h;
        g_wl[n][k0 + tx] = l;
    }
}

// ======================================================================
// GEMM1 (verified R7/R9 shape): CTA tile 128(M) x 256(N), split-K over z
// (9 splits), chunks of K=64. Per-chunk smem: xh,xl (16KB) + wh,wl (32KB)
// = 96KB, double-buffered (192KB). 8 warps as 2(M) x 4(N): warp tile
// 64x64. 3 bf16 passes (xh*wh + xh*wl + xl*wh) accumulated in fp32.
// ======================================================================
__global__ void __launch_bounds__(256, 1)
gemm_mma_kernel()
{
    extern __shared__ char dyn_smem[];
    const uint32_t base = (smem_u32(dyn_smem) + 1023u) & ~1023u;

    const int tid  = threadIdx.x;
    const int wid  = tid >> 5;
    const int lane = tid & 31;

    const int m0 = blockIdx.x * TM;
    const int n0 = blockIdx.y * TN;
    const int split = blockIdx.z;
    const int kbase = split * KSPLIT;

    const int mwarp = (wid >> 2) * 64;   // 0 or 64
    const int nwarp = (wid & 3) * 64;    // 0,64,128,192

    const int a_row = lane & 15;
    const int a_col = (lane >> 4) * 16;
    const int b_row = (lane & 7) + ((lane >> 4) << 3);
    const int b_col = ((lane >> 3) & 1) * 16;

    float c[4][8][4];
    #pragma unroll
    for (int i = 0; i < 4; i++)
        #pragma unroll
        for (int j = 0; j < 8; j++)
            #pragma unroll
            for (int e = 0; e < 4; e++) c[i][j][e] = 0.0f;

    const uint32_t BUFSZ = 98304u;   // 96 KB

    auto issue_loads = [&](int ch) {
        const int k0 = kbase + ch * CK;
        const uint32_t buf = base + ((ch & 1) ? BUFSZ : 0u);
        const __nv_bfloat16* axh = &g_xh[m0][k0];
        const __nv_bfloat16* axl = &g_xl[m0][k0];
        #pragma unroll
        for (int t = 0; t < 4; t++) {
            int q = tid + t * 256;
            int row = q >> 3, qc = q & 7;
            uint32_t off = SWZ128(row * 128 + qc * 16);
            cp_async16(buf +            off, axh + (size_t)row * KPAD + qc * 8);
            cp_async16(buf + 16384u +   off, axl + (size_t)row * KPAD + qc * 8);
        }
        const __nv_bfloat16* bwh = &g_wh[n0][k0];
        const __nv_bfloat16* bwl = &g_wl[n0][k0];
        #pragma unroll
        for (int t = 0; t < 8; t++) {
            int q = tid + t * 256;
            int row = q >> 3, qc = q & 7;
            uint32_t off = SWZ128(row * 128 + qc * 16);
            cp_async16(buf + 32768u + off, bwh + (size_t)row * KPAD + qc * 8);
            cp_async16(buf + 65536u + off, bwl + (size_t)row * KPAD + qc * 8);
        }
        CP_COMMIT();
    };

    issue_loads(0);

    for (int i = 0; i < NCHUNK; i++) {
        if (i + 1 < NCHUNK) { issue_loads(i + 1); CP_WAIT1(); }
        else                { CP_WAIT0(); }
        __syncthreads();

        const uint32_t buf = base + ((i & 1) ? BUFSZ : 0u);
        const uint32_t Ah = buf, Al = buf + 16384u;
        const uint32_t Bh = buf + 32768u, Bl = buf + 65536u;

        #pragma unroll
        for (int kk = 0; kk < 4; kk++) {
            uint32_t ah[4][4], al[4][4];
            #pragma unroll
            for (int t = 0; t < 4; t++) {
                uint32_t offA = SWZ128((mwarp + t * 16 + a_row) * 128 + kk * 32 + a_col);
                LDM_X4(ah[t][0], ah[t][1], ah[t][2], ah[t][3], Ah + offA);
                LDM_X4(al[t][0], al[t][1], al[t][2], al[t][3], Al + offA);
            }
            #pragma unroll
            for (int half = 0; half < 2; half++) {
                uint32_t bh[4][2], bl[4][2];
                #pragma unroll
                for (int t = 0; t < 2; t++) {
                    uint32_t offB = SWZ128((nwarp + half * 32 + t * 16 + b_row) * 128
                                           + kk * 32 + b_col);
                    LDM_X4(bh[2*t][0], bh[2*t][1], bh[2*t+1][0], bh[2*t+1][1], Bh + offB);
                    LDM_X4(bl[2*t][0], bl[2*t][1], bl[2*t+1][0], bl[2*t+1][1], Bl + offB);
                }
                #pragma unroll
                for (int mi = 0; mi < 4; mi++)
                    #pragma unroll
                    for (int nj = 0; nj < 4; nj++) {
                        float* acc = c[mi][half * 4 + nj];
                        mma_bf16(acc, ah[mi], bh[nj]);   // xh * wh
                        mma_bf16(acc, ah[mi], bl[nj]);   // xh * wl
                        mma_bf16(acc, al[mi], bh[nj]);   // xl * wh
                    }
            }
        }
        __syncthreads();
    }

    // epilogue: m16n8 frag -> rows (lane/4, +8), cols 2*(lane%4)
    const int er = lane >> 2;
    const int ec = (lane & 3) * 2;
    #pragma unroll
    for (int mi = 0; mi < 4; mi++) {
        const int row = m0 + mwarp + mi * 16 + er;
        #pragma unroll
        for (int nj = 0; nj < 8; nj++) {
            const int col = n0 + nwarp + nj * 8 + ec;
            *reinterpret_cast<float2*>(&g_hpart[split][row][col]) =
                make_float2(c[mi][nj][0], c[mi][nj][1]);
            *reinterpret_cast<float2*>(&g_hpart[split][row + 8][col]) =
                make_float2(c[mi][nj][2], c[mi][nj][3]);
        }
    }
}

// ======================================================================
// Stage 2 (verified 26us shape): one CTA per batch row.
// Reduce split-K partials, +b1, ReLU, then h @ W2 + b2.
// ======================================================================
__global__ void __launch_bounds__(256)
mlp2_kernel(const float* __restrict__ b1,
            const float* __restrict__ W2,
            const float* __restrict__ b2,
            float* __restrict__ out)
{
    __shared__ float hs[NHID];
    const int b   = blockIdx.x;
    const int tid = threadIdx.x;

    #pragma unroll
    for (int n = tid; n < NHID; n += 256) {
        float s = 0.0f;
        #pragma unroll
        for (int sp = 0; sp < SPLITK; sp++) s += g_hpart[sp][b][n];
        s += b1[n];
        hs[n] = fmaxf(s, 0.0f);
    }
    __syncthreads();

    if (tid < NOUT) {
        float a0 = 0.f, a1 = 0.f, a2 = 0.f, a3 = 0.f;
        #pragma unroll 8
        for (int n = 0; n < NHID; n += 4) {
            a0 = fmaf(hs[n + 0], W2[(n + 0) * NOUT + tid], a0);
            a1 = fmaf(hs[n + 1], W2[(n + 1) * NOUT + tid], a1);
            a2 = fmaf(hs[n + 2], W2[(n + 2) * NOUT + tid], a2);
            a3 = fmaf(hs[n + 3], W2[(n + 3) * NOUT + tid], a3);
        }
        out[b * NOUT + tid] = (a0 + a1) + (a2 + a3) + b2[tid];
    }
}

// ======================================================================
// kernel_launch — graph-capturable, allocation-free.
// Input order (metadata): st, at, st1, W1, b1, W2, b2. Output: float32.
// ======================================================================
extern "C" void kernel_launch(void* const* d_in, const int* in_sizes, int n_in,
                              void* d_out, int out_size)
{
    const float* st  = (const float*)d_in[0];
    const float* at  = (const float*)d_in[1];
    const float* st1 = (const float*)d_in[2];
    const float* W1  = (const float*)d_in[3];
    const float* b1  = (const float*)d_in[4];
    const float* W2  = (const float*)d_in[5];
    const float* b2  = (const float*)d_in[6];
    float* out = (float*)d_out;

    dim3 gx((KPAD + 2047) / 2048, NBATCH);
    convert_x_kernel<<<gx, 256>>>(st, at, st1);

    dim3 gw(KPAD / 32, NHID / 32);
    convert_w_kernel<<<gw, dim3(32, 8)>>>(W1);

    const int dyn_smem = 2 * 98304 + 1024;   // 192 KB + align slack
    cudaFuncSetAttribute(gemm_mma_kernel,
                         cudaFuncAttributeMaxDynamicSharedMemorySize, dyn_smem);
    dim3 gg(MT, NT, SPLITK);                 // 8 x 2 x 9 = 144 CTAs, one wave
    gemm_mma_kernel<<<gg, 256, dyn_smem>>>();

    mlp2_kernel<<<NBATCH, 256>>>(b1, W2, b2, out);
}